// round 1
// baseline (speedup 1.0000x reference)
#include <cuda_runtime.h>

#define NVOX 500000
#define CH 8
#define KT 27

// Ping-pong scratch for intermediate activations (16 MB each). Static device
// arrays: allocation-free per harness rules.
__device__ float g_bufA[NVOX * CH];
__device__ float g_bufB[NVOX * CH];

__device__ __forceinline__ void ffma2(unsigned long long& d,
                                      unsigned long long a,
                                      unsigned long long b) {
    asm volatile("fma.rn.f32x2 %0, %1, %2, %0;" : "+l"(d) : "l"(a), "l"(b));
}

__device__ __forceinline__ unsigned long long pack2(float x) {
    unsigned long long r;
    unsigned int xb = __float_as_uint(x);
    asm("mov.b64 %0, {%1, %1};" : "=l"(r) : "r"(xb));
    return r;
}

// One sparse-conv layer: out[n,:] = act( sum_k_valid x[nbr[n,k],:] @ W[k,:,:] ) (+resid)
// RELU: apply relu.  RES: add residual (mutually exclusive here).
template <bool RELU, bool RES>
__global__ void __launch_bounds__(256)
spconv_kernel(const float4* __restrict__ x,      // [NVOX][2] float4 (N x 8 f32)
              const int*    __restrict__ nbr,    // [NVOX][27]
              const float*  __restrict__ w,      // [27][8][8]
              const float4* __restrict__ resid,  // [NVOX][2] or null
              float4*       __restrict__ out)    // [NVOX][2]
{
    // Weights in shared as f32x2 pairs: sw[k*32 + c*4 + p] = (w[k][c][2p], w[k][c][2p+1])
    __shared__ __align__(16) unsigned long long sw[KT * 32];
    {
        const unsigned long long* w2 = (const unsigned long long*)w;
        for (int i = threadIdx.x; i < KT * 32; i += 256) sw[i] = w2[i];
    }
    __syncthreads();

    const int r0 = blockIdx.x * 512 + threadIdx.x;
    const int r1 = r0 + 256;
    const bool ok0 = (r0 < NVOX);
    const bool ok1 = (r1 < NVOX);

    unsigned long long acc0[4] = {0ull, 0ull, 0ull, 0ull};
    unsigned long long acc1[4] = {0ull, 0ull, 0ull, 0ull};

    const int* nb0 = nbr + (long long)r0 * KT;
    const int* nb1 = nbr + (long long)r1 * KT;

#pragma unroll
    for (int k = 0; k < KT; k++) {
        const int j0 = ok0 ? __ldg(nb0 + k) : -1;
        const int j1 = ok1 ? __ldg(nb1 + k) : -1;

        float4 a0 = make_float4(0.f, 0.f, 0.f, 0.f);
        float4 b0 = a0, a1 = a0, b1 = a0;
        if (j0 >= 0) { a0 = __ldg(x + j0 * 2); b0 = __ldg(x + j0 * 2 + 1); }
        if (j1 >= 0) { a1 = __ldg(x + j1 * 2); b1 = __ldg(x + j1 * 2 + 1); }

        unsigned long long p0[8], p1[8];
        p0[0] = pack2(a0.x); p0[1] = pack2(a0.y); p0[2] = pack2(a0.z); p0[3] = pack2(a0.w);
        p0[4] = pack2(b0.x); p0[5] = pack2(b0.y); p0[6] = pack2(b0.z); p0[7] = pack2(b0.w);
        p1[0] = pack2(a1.x); p1[1] = pack2(a1.y); p1[2] = pack2(a1.z); p1[3] = pack2(a1.w);
        p1[4] = pack2(b1.x); p1[5] = pack2(b1.y); p1[6] = pack2(b1.z); p1[7] = pack2(b1.w);

        const unsigned long long* wk = sw + k * 32;
#pragma unroll
        for (int c = 0; c < 8; c++) {
            // w[k][c][0..7] as 4 packed pairs (two 16B broadcast LDS)
            const ulonglong2 wA = *(const ulonglong2*)(wk + c * 4);
            const ulonglong2 wB = *(const ulonglong2*)(wk + c * 4 + 2);
            ffma2(acc0[0], p0[c], wA.x);
            ffma2(acc0[1], p0[c], wA.y);
            ffma2(acc0[2], p0[c], wB.x);
            ffma2(acc0[3], p0[c], wB.y);
            ffma2(acc1[0], p1[c], wA.x);
            ffma2(acc1[1], p1[c], wA.y);
            ffma2(acc1[2], p1[c], wB.x);
            ffma2(acc1[3], p1[c], wB.y);
        }
    }

    // Epilogue: unpack, activation / residual, store.
    float v0[8], v1[8];
#pragma unroll
    for (int i = 0; i < 4; i++) {
        unsigned int lo, hi;
        asm("mov.b64 {%0, %1}, %2;" : "=r"(lo), "=r"(hi) : "l"(acc0[i]));
        v0[2 * i] = __uint_as_float(lo);
        v0[2 * i + 1] = __uint_as_float(hi);
        asm("mov.b64 {%0, %1}, %2;" : "=r"(lo), "=r"(hi) : "l"(acc1[i]));
        v1[2 * i] = __uint_as_float(lo);
        v1[2 * i + 1] = __uint_as_float(hi);
    }

    if (ok0) {
        if (RES) {
            const float4 ra = resid[r0 * 2];
            const float4 rb = resid[r0 * 2 + 1];
            v0[0] += ra.x; v0[1] += ra.y; v0[2] += ra.z; v0[3] += ra.w;
            v0[4] += rb.x; v0[5] += rb.y; v0[6] += rb.z; v0[7] += rb.w;
        }
        if (RELU) {
#pragma unroll
            for (int i = 0; i < 8; i++) v0[i] = fmaxf(v0[i], 0.f);
        }
        out[r0 * 2]     = make_float4(v0[0], v0[1], v0[2], v0[3]);
        out[r0 * 2 + 1] = make_float4(v0[4], v0[5], v0[6], v0[7]);
    }
    if (ok1) {
        if (RES) {
            const float4 ra = resid[r1 * 2];
            const float4 rb = resid[r1 * 2 + 1];
            v1[0] += ra.x; v1[1] += ra.y; v1[2] += ra.z; v1[3] += ra.w;
            v1[4] += rb.x; v1[5] += rb.y; v1[6] += rb.z; v1[7] += rb.w;
        }
        if (RELU) {
#pragma unroll
            for (int i = 0; i < 8; i++) v1[i] = fmaxf(v1[i], 0.f);
        }
        out[r1 * 2]     = make_float4(v1[0], v1[1], v1[2], v1[3]);
        out[r1 * 2 + 1] = make_float4(v1[4], v1[5], v1[6], v1[7]);
    }
}

extern "C" void kernel_launch(void* const* d_in, const int* in_sizes, int n_in,
                              void* d_out, int out_size) {
    (void)in_sizes; (void)n_in; (void)out_size;
    const float* feats0 = (const float*)d_in[0];
    const float* feats1 = (const float*)d_in[1];
    const float* W0     = (const float*)d_in[2];  // [3][27][8][8]
    const float* W1     = (const float*)d_in[3];
    const int*   nbr0   = (const int*)d_in[4];    // [N][27]
    const int*   nbr1   = (const int*)d_in[5];
    float* out = (float*)d_out;

    float *bufA, *bufB;
    cudaGetSymbolAddress((void**)&bufA, g_bufA);
    cudaGetSymbolAddress((void**)&bufB, g_bufB);

    const int grid = (NVOX + 511) / 512;
    const int block = 256;
    const int LW = KT * CH * CH;  // 1728 floats per layer

    // Grid 0
    spconv_kernel<true,  false><<<grid, block>>>((const float4*)feats0, nbr0, W0,          nullptr,               (float4*)bufA);
    spconv_kernel<true,  false><<<grid, block>>>((const float4*)bufA,   nbr0, W0 + LW,     nullptr,               (float4*)bufB);
    spconv_kernel<false, true ><<<grid, block>>>((const float4*)bufB,   nbr0, W0 + 2 * LW, (const float4*)feats0, (float4*)out);
    // Grid 1
    spconv_kernel<true,  false><<<grid, block>>>((const float4*)feats1, nbr1, W1,          nullptr,               (float4*)bufA);
    spconv_kernel<true,  false><<<grid, block>>>((const float4*)bufA,   nbr1, W1 + LW,     nullptr,               (float4*)bufB);
    spconv_kernel<false, true ><<<grid, block>>>((const float4*)bufB,   nbr1, W1 + 2 * LW, (const float4*)feats1, (float4*)out + NVOX * 2);
}

// round 2
// speedup vs baseline: 1.1331x; 1.1331x over previous
#include <cuda_runtime.h>

#define NVOX 500000
#define CH 8
#define KT 27
#define TPB 256

// Ping-pong scratch for intermediate activations (16 MB each).
__device__ float g_bufA[NVOX * CH];
__device__ float g_bufB[NVOX * CH];

__device__ __forceinline__ void ffma2(unsigned long long& d,
                                      unsigned long long a,
                                      unsigned long long b) {
    asm volatile("fma.rn.f32x2 %0, %1, %2, %0;" : "+l"(d) : "l"(a), "l"(b));
}

__device__ __forceinline__ unsigned long long pack2(float x) {
    unsigned long long r;
    unsigned int xb = __float_as_uint(x);
    asm("mov.b64 %0, {%1, %1};" : "=l"(r) : "r"(xb));
    return r;
}

// One sparse-conv layer, thread-per-row, nbr staged coalesced through shared,
// gathers batched 9 taps deep for MLP.
template <bool RELU, bool RES>
__global__ void __launch_bounds__(TPB)
spconv_kernel(const float4* __restrict__ x,      // [NVOX][2] float4
              const int*    __restrict__ nbr,    // [NVOX][27]
              const float*  __restrict__ w,      // [27][8][8]
              const float4* __restrict__ resid,  // [NVOX][2] or null
              float4*       __restrict__ out)    // [NVOX][2]
{
    // Weights as f32x2 pairs: sw[k*32 + cin*4 + p] = (w[k][cin][2p], w[k][cin][2p+1])
    __shared__ __align__(16) unsigned long long sw[KT * 32];   // 6912 B
    __shared__ __align__(16) int snbr[TPB * KT];               // 27648 B

    {
        const unsigned long long* w2 = (const unsigned long long*)w;
        for (int i = threadIdx.x; i < KT * 32; i += TPB) sw[i] = w2[i];
    }

    const int base = blockIdx.x * TPB;
    const int rows = min(TPB, NVOX - base);
    {
        // Contiguous block slice of nbr: rows*27 ints, 16B aligned (base%256==0).
        const int nints = rows * KT;            // 6912 or 864 -> both %4 == 0
        const int4* src = (const int4*)(nbr + (long long)base * KT);
        int4* dst = (int4*)snbr;
        const int nvec = nints >> 2;
        for (int i = threadIdx.x; i < nvec; i += TPB) dst[i] = src[i];
    }
    __syncthreads();

    const int r = base + threadIdx.x;
    const bool ok = (r < NVOX);
    const int* myn = snbr + threadIdx.x * KT;   // stride 27 ints -> conflict-free

    unsigned long long acc[4] = {0ull, 0ull, 0ull, 0ull};

#pragma unroll
    for (int g = 0; g < KT; g += 9) {
        int j[9];
#pragma unroll
        for (int t = 0; t < 9; t++) j[t] = ok ? myn[g + t] : -1;

        // Issue all 18 gather loads of this group before any FMA (MLP ~18).
        float4 A[9], B[9];
#pragma unroll
        for (int t = 0; t < 9; t++) {
            A[t] = make_float4(0.f, 0.f, 0.f, 0.f);
            B[t] = A[t];
            if (j[t] >= 0) {
                A[t] = __ldg(x + j[t] * 2);
                B[t] = __ldg(x + j[t] * 2 + 1);
            }
        }

#pragma unroll
        for (int t = 0; t < 9; t++) {
            const unsigned long long* wk = sw + (g + t) * 32;
            float f[8] = {A[t].x, A[t].y, A[t].z, A[t].w,
                          B[t].x, B[t].y, B[t].z, B[t].w};
#pragma unroll
            for (int c = 0; c < 8; c++) {
                const unsigned long long p = pack2(f[c]);
                const ulonglong2 wA = *(const ulonglong2*)(wk + c * 4);
                const ulonglong2 wB = *(const ulonglong2*)(wk + c * 4 + 2);
                ffma2(acc[0], p, wA.x);
                ffma2(acc[1], p, wA.y);
                ffma2(acc[2], p, wB.x);
                ffma2(acc[3], p, wB.y);
            }
        }
    }

    // Epilogue: unpack, residual / relu, store.
    float v[8];
#pragma unroll
    for (int i = 0; i < 4; i++) {
        unsigned int lo, hi;
        asm("mov.b64 {%0, %1}, %2;" : "=r"(lo), "=r"(hi) : "l"(acc[i]));
        v[2 * i]     = __uint_as_float(lo);
        v[2 * i + 1] = __uint_as_float(hi);
    }

    if (ok) {
        if (RES) {
            const float4 ra = resid[r * 2];
            const float4 rb = resid[r * 2 + 1];
            v[0] += ra.x; v[1] += ra.y; v[2] += ra.z; v[3] += ra.w;
            v[4] += rb.x; v[5] += rb.y; v[6] += rb.z; v[7] += rb.w;
        }
        if (RELU) {
#pragma unroll
            for (int i = 0; i < 8; i++) v[i] = fmaxf(v[i], 0.f);
        }
        out[r * 2]     = make_float4(v[0], v[1], v[2], v[3]);
        out[r * 2 + 1] = make_float4(v[4], v[5], v[6], v[7]);
    }
}

extern "C" void kernel_launch(void* const* d_in, const int* in_sizes, int n_in,
                              void* d_out, int out_size) {
    (void)in_sizes; (void)n_in; (void)out_size;
    const float* feats0 = (const float*)d_in[0];
    const float* feats1 = (const float*)d_in[1];
    const float* W0     = (const float*)d_in[2];  // [3][27][8][8]
    const float* W1     = (const float*)d_in[3];
    const int*   nbr0   = (const int*)d_in[4];    // [N][27]
    const int*   nbr1   = (const int*)d_in[5];
    float* out = (float*)d_out;

    float *bufA, *bufB;
    cudaGetSymbolAddress((void**)&bufA, g_bufA);
    cudaGetSymbolAddress((void**)&bufB, g_bufB);

    const int grid = (NVOX + TPB - 1) / TPB;
    const int LW = KT * CH * CH;  // 1728 floats per layer

    // Grid 0
    spconv_kernel<true,  false><<<grid, TPB>>>((const float4*)feats0, nbr0, W0,          nullptr,               (float4*)bufA);
    spconv_kernel<true,  false><<<grid, TPB>>>((const float4*)bufA,   nbr0, W0 + LW,     nullptr,               (float4*)bufB);
    spconv_kernel<false, true ><<<grid, TPB>>>((const float4*)bufB,   nbr0, W0 + 2 * LW, (const float4*)feats0, (float4*)out);
    // Grid 1
    spconv_kernel<true,  false><<<grid, TPB>>>((const float4*)feats1, nbr1, W1,          nullptr,               (float4*)bufA);
    spconv_kernel<true,  false><<<grid, TPB>>>((const float4*)bufA,   nbr1, W1 + LW,     nullptr,               (float4*)bufB);
    spconv_kernel<false, true ><<<grid, TPB>>>((const float4*)bufB,   nbr1, W1 + 2 * LW, (const float4*)feats1, (float4*)out + NVOX * 2);
}

// round 3
// speedup vs baseline: 1.3543x; 1.1952x over previous
#include <cuda_runtime.h>

#define NVOX 500000
#define CH 8
#define KT 27
#define TPB 128
#define RPT 4                      // rows per thread
#define RPB (TPB * RPT)            // 512 rows per block

// Ping-pong scratch for intermediate activations (16 MB each).
__device__ float g_bufA[NVOX * CH];
__device__ float g_bufB[NVOX * CH];

// dynamic smem layout: [ sw: 27*32 u64 (6912 B) | snbr: RPB*27 int (55296 B) ]
#define SW_U64 (KT * 32)
#define SMEM_BYTES (SW_U64 * 8 + RPB * KT * 4)

__device__ __forceinline__ void ffma2(unsigned long long& d,
                                      unsigned long long a,
                                      unsigned long long b) {
    asm volatile("fma.rn.f32x2 %0, %1, %2, %0;" : "+l"(d) : "l"(a), "l"(b));
}

__device__ __forceinline__ unsigned long long pack2(float x) {
    unsigned long long r;
    unsigned int xb = __float_as_uint(x);
    asm("mov.b64 %0, {%1, %1};" : "=l"(r) : "r"(xb));
    return r;
}

template <bool RELU, bool RES>
__global__ void __launch_bounds__(TPB)
spconv_kernel(const float4* __restrict__ x,      // [NVOX][2] float4
              const int*    __restrict__ nbr,    // [NVOX][27]
              const float*  __restrict__ w,      // [27][8][8]
              const float4* __restrict__ resid,  // [NVOX][2] or null
              float4*       __restrict__ out)    // [NVOX][2]
{
    extern __shared__ __align__(16) unsigned char smem[];
    unsigned long long* sw = (unsigned long long*)smem;       // 27*32 u64
    int* snbr = (int*)(smem + SW_U64 * 8);                    // RPB*27 int

    {
        const unsigned long long* w2 = (const unsigned long long*)w;
#pragma unroll
        for (int i = threadIdx.x; i < SW_U64; i += TPB) sw[i] = w2[i];
    }

    const int base = blockIdx.x * RPB;
    const int rows = min(RPB, NVOX - base);
    {
        const int nvec = (rows * KT) >> 2;   // rows*27 always %4==0 here
        const int4* src = (const int4*)(nbr + (long long)base * KT);
        int4* dst = (int4*)snbr;
        for (int i = threadIdx.x; i < nvec; i += TPB) dst[i] = src[i];
    }
    __syncthreads();

    const int t = threadIdx.x;
    int r[RPT];
    bool ok[RPT];
    const int* myn[RPT];
#pragma unroll
    for (int s = 0; s < RPT; s++) {
        r[s] = base + t + TPB * s;
        ok[s] = (r[s] < NVOX);
        myn[s] = snbr + (t + TPB * s) * KT;
    }

    unsigned long long acc[RPT][4];
#pragma unroll
    for (int s = 0; s < RPT; s++)
#pragma unroll
        for (int q = 0; q < 4; q++) acc[s][q] = 0ull;

    float4 A0[RPT], B0[RPT], A1[RPT], B1[RPT];

    // ---- tap load: issue all 2*RPT gathers of tap k ----
#define LOAD_TAP(k, A, B)                                        \
    {                                                            \
        _Pragma("unroll")                                        \
        for (int s = 0; s < RPT; s++) {                          \
            const int j = ok[s] ? myn[s][(k)] : -1;              \
            A[s] = make_float4(0.f, 0.f, 0.f, 0.f);              \
            B[s] = A[s];                                         \
            if (j >= 0) {                                        \
                A[s] = __ldg(x + j * 2);                         \
                B[s] = __ldg(x + j * 2 + 1);                     \
            }                                                    \
        }                                                        \
    }

    // ---- tap fma: weights loaded once per (k,c), reused by all RPT rows ----
#define FMA_TAP(k, A, B)                                                    \
    {                                                                       \
        const unsigned long long* wk = sw + (k) * 32;                       \
        _Pragma("unroll")                                                   \
        for (int c = 0; c < 8; c++) {                                       \
            const ulonglong2 wA = *(const ulonglong2*)(wk + c * 4);         \
            const ulonglong2 wB = *(const ulonglong2*)(wk + c * 4 + 2);     \
            _Pragma("unroll")                                               \
            for (int s = 0; s < RPT; s++) {                                 \
                float f;                                                    \
                switch (c) {                                                \
                    case 0: f = A[s].x; break;                              \
                    case 1: f = A[s].y; break;                              \
                    case 2: f = A[s].z; break;                              \
                    case 3: f = A[s].w; break;                              \
                    case 4: f = B[s].x; break;                              \
                    case 5: f = B[s].y; break;                              \
                    case 6: f = B[s].z; break;                              \
                    default: f = B[s].w; break;                             \
                }                                                           \
                const unsigned long long p = pack2(f);                      \
                ffma2(acc[s][0], p, wA.x);                                  \
                ffma2(acc[s][1], p, wA.y);                                  \
                ffma2(acc[s][2], p, wB.x);                                  \
                ffma2(acc[s][3], p, wB.y);                                  \
            }                                                               \
        }                                                                   \
    }

    // Software-pipelined tap loop: 2 taps in flight.
    LOAD_TAP(0, A0, B0);
#pragma unroll 1
    for (int k = 0; k < 26; k += 2) {
        LOAD_TAP(k + 1, A1, B1);
        FMA_TAP(k, A0, B0);
        LOAD_TAP(k + 2, A0, B0);
        FMA_TAP(k + 1, A1, B1);
    }
    FMA_TAP(26, A0, B0);

    // Epilogue
#pragma unroll
    for (int s = 0; s < RPT; s++) {
        if (!ok[s]) continue;
        float v[8];
#pragma unroll
        for (int i = 0; i < 4; i++) {
            unsigned int lo, hi;
            asm("mov.b64 {%0, %1}, %2;" : "=r"(lo), "=r"(hi) : "l"(acc[s][i]));
            v[2 * i]     = __uint_as_float(lo);
            v[2 * i + 1] = __uint_as_float(hi);
        }
        if (RES) {
            const float4 ra = resid[r[s] * 2];
            const float4 rb = resid[r[s] * 2 + 1];
            v[0] += ra.x; v[1] += ra.y; v[2] += ra.z; v[3] += ra.w;
            v[4] += rb.x; v[5] += rb.y; v[6] += rb.z; v[7] += rb.w;
        }
        if (RELU) {
#pragma unroll
            for (int i = 0; i < 8; i++) v[i] = fmaxf(v[i], 0.f);
        }
        out[r[s] * 2]     = make_float4(v[0], v[1], v[2], v[3]);
        out[r[s] * 2 + 1] = make_float4(v[4], v[5], v[6], v[7]);
    }
#undef LOAD_TAP
#undef FMA_TAP
}

extern "C" void kernel_launch(void* const* d_in, const int* in_sizes, int n_in,
                              void* d_out, int out_size) {
    (void)in_sizes; (void)n_in; (void)out_size;
    const float* feats0 = (const float*)d_in[0];
    const float* feats1 = (const float*)d_in[1];
    const float* W0     = (const float*)d_in[2];  // [3][27][8][8]
    const float* W1     = (const float*)d_in[3];
    const int*   nbr0   = (const int*)d_in[4];    // [N][27]
    const int*   nbr1   = (const int*)d_in[5];
    float* out = (float*)d_out;

    float *bufA, *bufB;
    cudaGetSymbolAddress((void**)&bufA, g_bufA);
    cudaGetSymbolAddress((void**)&bufB, g_bufB);

    cudaFuncSetAttribute(spconv_kernel<true, false>,
                         cudaFuncAttributeMaxDynamicSharedMemorySize, SMEM_BYTES);
    cudaFuncSetAttribute(spconv_kernel<false, true>,
                         cudaFuncAttributeMaxDynamicSharedMemorySize, SMEM_BYTES);

    const int grid = (NVOX + RPB - 1) / RPB;
    const int LW = KT * CH * CH;  // 1728 floats per layer

    // Grid 0
    spconv_kernel<true,  false><<<grid, TPB, SMEM_BYTES>>>((const float4*)feats0, nbr0, W0,          nullptr,               (float4*)bufA);
    spconv_kernel<true,  false><<<grid, TPB, SMEM_BYTES>>>((const float4*)bufA,   nbr0, W0 + LW,     nullptr,               (float4*)bufB);
    spconv_kernel<false, true ><<<grid, TPB, SMEM_BYTES>>>((const float4*)bufB,   nbr0, W0 + 2 * LW, (const float4*)feats0, (float4*)out);
    // Grid 1
    spconv_kernel<true,  false><<<grid, TPB, SMEM_BYTES>>>((const float4*)feats1, nbr1, W1,          nullptr,               (float4*)bufA);
    spconv_kernel<true,  false><<<grid, TPB, SMEM_BYTES>>>((const float4*)bufA,   nbr1, W1 + LW,     nullptr,               (float4*)bufB);
    spconv_kernel<false, true ><<<grid, TPB, SMEM_BYTES>>>((const float4*)bufB,   nbr1, W1 + 2 * LW, (const float4*)feats1, (float4*)out + NVOX * 2);
}